// round 2
// baseline (speedup 1.0000x reference)
#include <cuda_runtime.h>
#include <math.h>

// ---------------------------------------------------------------------------
// S4D SSM, 4 shared layers. H=511 channels, L=2048, N=32 complex modes.
// FFT conv replaced by the exact 32-mode linear recurrence
//   s_n[l] = w_n * s_n[l-1] + z[l],  y[l] = 2*Re(sum_n c_n s_n[l])
// (one warp per channel, one lane per mode), then fp32 tiled GEMM for the
// GLU projection (double-buffered, 2-way-conflict fragments), fused
// GLU+residual, and channel LayerNorm.
// ---------------------------------------------------------------------------

namespace {
constexpr int H  = 511;
constexpr int L  = 2048;
constexpr int NSTATE = 32;
constexpr int M2 = 2 * H;       // 1022 GLU output rows
constexpr int HL = H * L;
constexpr int KTILES = (H + 7) / 8;   // 64
}

// Scratch (static device globals: no allocations allowed)
__device__ float g_y1[HL];       // post-SSM+gelu activations; reused as zmid
__device__ float g_y2[2 * HL];   // GLU pre-activation (1022 x 2048)
__device__ float g_zA[HL];
__device__ float g_zB[HL];

// ---------------------------------------------------------------------------
// Kernel 1: SSM scan + D-skip + tanh-GELU.  One warp per channel h; lane = mode n.
// ---------------------------------------------------------------------------
__global__ __launch_bounds__(128) void scan_kernel(
    const float* __restrict__ zin, const float* __restrict__ log_dt,
    const float* __restrict__ Arl, const float* __restrict__ Aim,
    const float* __restrict__ Cre, const float* __restrict__ Cim,
    const float* __restrict__ Dsk, float* __restrict__ y1) {
  __shared__ float s_contrib[4][32 * 33];   // [t][n] padded: conflict-free both ways
  __shared__ float s_z[4][32];

  const int w    = threadIdx.x >> 5;
  const int lane = threadIdx.x & 31;
  const int h    = blockIdx.x * 4 + w;
  if (h >= H) return;                       // per-warp exit, no __syncthreads used

  // --- per-(h,n) ZOH discretization parameters, computed inline ---
  const int hn   = h * NSTATE + lane;
  const float dt = expf(log_dt[h]);
  const float Are = -expf(Arl[hn]);
  const float Ai  = Aim[hn];
  const float ar  = Are * dt;               // dtA
  const float ai  = Ai * dt;
  const float er  = expf(ar);
  float sb, cbv;
  sincosf(ai, &sb, &cbv);
  const float wr = er * cbv;                // w = exp(dtA)
  const float wi = er * sb;
  const float den = Are * Are + Ai * Ai;
  const float wm1 = wr - 1.0f;
  const float qr = (wm1 * Are + wi * Ai) / den;   // (w-1)/A
  const float qi = (wi * Are - wm1 * Ai) / den;
  const float Cr = Cre[hn], Ci = Cim[hn];
  const float cr  = Cr * qr - Ci * qi;      // Ccoef
  const float ci  = Cr * qi + Ci * qr;
  const float nci = -ci;
  const float nwi = -wi;
  const float D   = Dsk[h];

  float sr = 0.0f, si = 0.0f;
  float* cb = s_contrib[w];
  float* zb = s_z[w];
  const float* zrow = zin + (size_t)h * L;
  float*       yrow = y1  + (size_t)h * L;

  for (int t0 = 0; t0 < L; t0 += 32) {
    const float zv = zrow[t0 + lane];
    zb[lane] = zv;
    __syncwarp();

    // hoist all 32 broadcast loads into registers (batched LDS, MLP)
    float z32[32];
#pragma unroll
    for (int t = 0; t < 32; t++) z32[t] = zb[t];

    // serial recurrence over 32 steps; contribution staged to smem
#pragma unroll
    for (int t = 0; t < 32; t++) {
      const float nsr = fmaf(wr, sr, fmaf(nwi, si, z32[t]));
      const float nsi = fmaf(wr, si, wi * sr);
      sr = nsr; si = nsi;
      cb[t * 33 + lane] = fmaf(cr, sr, nci * si);   // Re(c * s)
    }
    __syncwarp();

    // lane <-> timestep transpose reduce: lane sums its timestep over 32 modes
    float a0 = 0.f, a1 = 0.f, a2 = 0.f, a3 = 0.f;
    const int base = lane * 33;
#pragma unroll
    for (int n = 0; n < 32; n += 4) {
      a0 += cb[base + n];
      a1 += cb[base + n + 1];
      a2 += cb[base + n + 2];
      a3 += cb[base + n + 3];
    }
    float y = fmaf(D, zv, 2.0f * ((a0 + a1) + (a2 + a3)));

    // gelu (tanh approximation, matching jax.nn.gelu default)
    const float u  = 0.7978845608028654f * fmaf(0.044715f * y, y * y, y);
    const float gl = 0.5f * y * (1.0f + tanhf(u));
    yrow[t0 + lane] = gl;
    __syncwarp();
  }
}

// ---------------------------------------------------------------------------
// Kernel 2: Y2 = glu_w(1022x511) @ Y1(511x2048) + b.
// 128x128x8 tiles, 8x8 per thread, double-buffered smem, 2-way-conflict frags.
// ---------------------------------------------------------------------------
__global__ __launch_bounds__(256) void gemm_kernel(
    const float* __restrict__ W, const float* __restrict__ bias,
    const float* __restrict__ Y1, float* __restrict__ Y2) {
  __shared__ float As[2][8][128];   // [buf][k][m]
  __shared__ float Bs[2][8][128];   // [buf][k][n]
  const int lid = threadIdx.x;
  const int m0  = blockIdx.y * 128;
  const int n0  = blockIdx.x * 128;
  const int tx  = lid & 15;         // column group
  const int ty  = lid >> 4;         // row group

  float acc[8][8];
#pragma unroll
  for (int i = 0; i < 8; i++)
#pragma unroll
    for (int j = 0; j < 8; j++) acc[i][j] = 0.0f;

  float ar[4], br[4];

  // ---- prefetch tile 0 into registers ----
#pragma unroll
  for (int i = 0; i < 4; i++) {
    const int idx = lid + i * 256;          // W tile: 128 m x 8 k
    const int k = idx & 7, m = idx >> 3;
    const int gm = m0 + m, gk = k;
    ar[i] = (gm < M2 && gk < H) ? W[gm * H + gk] : 0.0f;
  }
#pragma unroll
  for (int i = 0; i < 4; i++) {
    const int idx = lid + i * 256;          // Y1 tile: 8 k x 128 n (coalesced)
    const int n = idx & 127, k = idx >> 7;
    br[i] = (k < H) ? Y1[k * L + n0 + n] : 0.0f;
  }
  // ---- store tile 0 ----
#pragma unroll
  for (int i = 0; i < 4; i++) {
    const int idx = lid + i * 256;
    As[0][idx & 7][idx >> 3] = ar[i];
  }
#pragma unroll
  for (int i = 0; i < 4; i++) {
    const int idx = lid + i * 256;
    Bs[0][idx >> 7][idx & 127] = br[i];
  }
  __syncthreads();

  for (int kt = 0; kt < KTILES; kt++) {
    const int cur = kt & 1, nxt = cur ^ 1;
    const int k0n = (kt + 1) * 8;
    const bool more = (kt + 1 < KTILES);

    // prefetch next tile into registers (overlaps with compute below)
    if (more) {
#pragma unroll
      for (int i = 0; i < 4; i++) {
        const int idx = lid + i * 256;
        const int k = idx & 7, m = idx >> 3;
        const int gm = m0 + m, gk = k0n + k;
        ar[i] = (gm < M2 && gk < H) ? W[gm * H + gk] : 0.0f;
      }
#pragma unroll
      for (int i = 0; i < 4; i++) {
        const int idx = lid + i * 256;
        const int n = idx & 127, k = idx >> 7;
        const int gk = k0n + k;
        br[i] = (gk < H) ? Y1[gk * L + n0 + n] : 0.0f;
      }
    }

    // compute on current buffer
#pragma unroll
    for (int k = 0; k < 8; k++) {
      // A fragment: rows ty*8..ty*8+7 (broadcast within warp: 2 ty values)
      const float4 a0 = *reinterpret_cast<const float4*>(&As[cur][k][ty * 8]);
      const float4 a1 = *reinterpret_cast<const float4*>(&As[cur][k][ty * 8 + 4]);
      // B fragment: cols tx*4..+3 and 64+tx*4..+3 (16B stride -> 2-way max)
      const float4 b0 = *reinterpret_cast<const float4*>(&Bs[cur][k][tx * 4]);
      const float4 b1 = *reinterpret_cast<const float4*>(&Bs[cur][k][64 + tx * 4]);
      const float av[8] = {a0.x, a0.y, a0.z, a0.w, a1.x, a1.y, a1.z, a1.w};
      const float bv[8] = {b0.x, b0.y, b0.z, b0.w, b1.x, b1.y, b1.z, b1.w};
#pragma unroll
      for (int i = 0; i < 8; i++)
#pragma unroll
        for (int j = 0; j < 8; j++) acc[i][j] = fmaf(av[i], bv[j], acc[i][j]);
    }

    // store next tile (safe: everyone finished reading nxt at the last barrier)
    if (more) {
#pragma unroll
      for (int i = 0; i < 4; i++) {
        const int idx = lid + i * 256;
        As[nxt][idx & 7][idx >> 3] = ar[i];
      }
#pragma unroll
      for (int i = 0; i < 4; i++) {
        const int idx = lid + i * 256;
        Bs[nxt][idx >> 7][idx & 127] = br[i];
      }
    }
    __syncthreads();
  }

  // epilogue: rows ty*8+i; cols n0+tx*4+j (j<4) and n0+64+tx*4+(j-4)
#pragma unroll
  for (int i = 0; i < 8; i++) {
    const int gm = m0 + ty * 8 + i;
    if (gm < M2) {
      const float bsv = bias[gm];
      float4 o0, o1;
      o0.x = acc[i][0] + bsv; o0.y = acc[i][1] + bsv;
      o0.z = acc[i][2] + bsv; o0.w = acc[i][3] + bsv;
      o1.x = acc[i][4] + bsv; o1.y = acc[i][5] + bsv;
      o1.z = acc[i][6] + bsv; o1.w = acc[i][7] + bsv;
      float* orow = Y2 + (size_t)gm * L + n0;
      *reinterpret_cast<float4*>(orow + tx * 4)      = o0;
      *reinterpret_cast<float4*>(orow + 64 + tx * 4) = o1;
    }
  }
}

// ---------------------------------------------------------------------------
// Kernel 3: GLU + residual.  zmid = y2[:H]*sigmoid(y2[H:]) + zin
// ---------------------------------------------------------------------------
__global__ __launch_bounds__(256) void glu_res_kernel(
    const float* __restrict__ Y2, const float* __restrict__ zin,
    float* __restrict__ zmid) {
  const int idx = blockIdx.x * 256 + threadIdx.x;
  if (idx >= HL) return;
  const float aa = Y2[idx];
  const float gg = Y2[idx + HL];          // (h+H)*L + l == idx + H*L
  const float s  = 1.0f / (1.0f + expf(-gg));
  zmid[idx] = fmaf(aa, s, zin[idx]);
}

// ---------------------------------------------------------------------------
// Kernel 4: LayerNorm over channels (per time index l).  Block: 32 cols x 8 rows.
// ---------------------------------------------------------------------------
__global__ __launch_bounds__(256) void ln_kernel(
    const float* __restrict__ zm, const float* __restrict__ gw,
    const float* __restrict__ bw, float* __restrict__ zout) {
  __shared__ float ssum[8][32];
  __shared__ float ssq[8][32];
  const int tx = threadIdx.x, ty = threadIdx.y;
  const int l  = blockIdx.x * 32 + tx;

  float s = 0.0f, q = 0.0f;
  for (int hh = ty; hh < H; hh += 8) {
    const float v = zm[hh * L + l];
    s += v;
    q = fmaf(v, v, q);
  }
  ssum[ty][tx] = s;
  ssq[ty][tx]  = q;
  __syncthreads();

  float S = 0.0f, Q = 0.0f;
#pragma unroll
  for (int j = 0; j < 8; j++) { S += ssum[j][tx]; Q += ssq[j][tx]; }
  const float mu  = S * (1.0f / (float)H);
  const float var = Q * (1.0f / (float)H) - mu * mu;
  const float inv = rsqrtf(var + 1e-5f);

  for (int hh = ty; hh < H; hh += 8) {
    const float v = zm[hh * L + l];
    zout[hh * L + l] = fmaf((v - mu) * inv, gw[hh], bw[hh]);
  }
}

// ---------------------------------------------------------------------------
extern "C" void kernel_launch(void* const* d_in, const int* in_sizes, int n_in,
                              void* d_out, int out_size) {
  const float* Z      = (const float*)d_in[0];
  const float* log_dt = (const float*)d_in[1];
  const float* Arl    = (const float*)d_in[2];
  const float* Aim    = (const float*)d_in[3];
  const float* Cre    = (const float*)d_in[4];
  const float* Cim    = (const float*)d_in[5];
  const float* Dsk    = (const float*)d_in[6];
  const float* Wg     = (const float*)d_in[7];
  const float* bg     = (const float*)d_in[8];
  const float* lng    = (const float*)d_in[9];
  const float* lnb    = (const float*)d_in[10];
  float* out = (float*)d_out;

  float *y1, *y2, *zA, *zB;
  cudaGetSymbolAddress((void**)&y1, g_y1);
  cudaGetSymbolAddress((void**)&y2, g_y2);
  cudaGetSymbolAddress((void**)&zA, g_zA);
  cudaGetSymbolAddress((void**)&zB, g_zB);

  const float* zin = Z;
  for (int layer = 0; layer < 4; layer++) {
    float* zout = (layer == 3) ? out : ((layer & 1) ? zB : zA);
    scan_kernel<<<(H + 3) / 4, 128>>>(zin, log_dt, Arl, Aim, Cre, Cim, Dsk, y1);
    gemm_kernel<<<dim3(L / 128, (M2 + 127) / 128), 256>>>(Wg, bg, y1, y2);
    glu_res_kernel<<<(HL + 255) / 256, 256>>>(y2, zin, y1);  // zmid reuses y1
    ln_kernel<<<L / 32, dim3(32, 8)>>>(y1, lng, lnb, zout);
    zin = zout;
  }
}

// round 3
// speedup vs baseline: 1.4008x; 1.4008x over previous
#include <cuda_runtime.h>
#include <cuda_bf16.h>
#include <mma.h>
#include <math.h>

using namespace nvcuda;

// ---------------------------------------------------------------------------
// S4D SSM, 4 shared layers. H=511, L=2048, N=32 complex modes.
//  K1: exact 32-mode recurrence (replaces FFT conv) + D-skip + GELU,
//      emitting bf16 hi/lo split activations (padded to 512 rows).
//  K2: GLU GEMM on tensor cores: C = W @ Y via 3-product bf16 split
//      (Whi*Yhi + Wlo*Yhi + Whi*Ylo), fp32 accumulate. wmma 16x16x16.
//  K3: fused bias + GLU + residual + channel LayerNorm (smem-staged).
// ---------------------------------------------------------------------------

namespace {
constexpr int H   = 511;
constexpr int L   = 2048;
constexpr int NST = 32;
constexpr int M2  = 2 * H;         // 1022
constexpr int HL  = H * L;
constexpr int KP  = 512;           // padded K
constexpr int MP  = 1024;          // padded M2
}

// Scratch (static device globals: no allocation allowed)
__device__ __nv_bfloat16 g_whi[MP * KP];
__device__ __nv_bfloat16 g_wlo[MP * KP];
__device__ __nv_bfloat16 g_yhi[KP * L];
__device__ __nv_bfloat16 g_ylo[KP * L];
__device__ float g_y2[MP * L];     // GLU pre-activation (padded rows are zero)
__device__ float g_zA[HL];
__device__ float g_zB[HL];

// ---------------------------------------------------------------------------
// Kernel 0: convert W (1022x511 f32) -> padded bf16 hi/lo (1024x512)
// ---------------------------------------------------------------------------
__global__ __launch_bounds__(256) void convw_kernel(const float* __restrict__ W) {
  const int idx = blockIdx.x * 256 + threadIdx.x;   // over MP*KP
  const int m = idx >> 9, k = idx & 511;
  const float v = (m < M2 && k < H) ? W[m * H + k] : 0.0f;
  const __nv_bfloat16 hi = __float2bfloat16(v);
  g_whi[idx] = hi;
  g_wlo[idx] = __float2bfloat16(v - __bfloat162float(hi));
}

// ---------------------------------------------------------------------------
// Kernel 1: SSM scan + D-skip + tanh-GELU -> bf16 hi/lo.
// One warp per channel h; lane = mode n. h==511 writes zero padding.
// ---------------------------------------------------------------------------
__global__ __launch_bounds__(128) void scan_kernel(
    const float* __restrict__ zin, const float* __restrict__ log_dt,
    const float* __restrict__ Arl, const float* __restrict__ Aim,
    const float* __restrict__ Cre, const float* __restrict__ Cim,
    const float* __restrict__ Dsk) {
  __shared__ float s_contrib[4][32 * 33];
  __shared__ float s_z[4][32];

  const int w    = threadIdx.x >> 5;
  const int lane = threadIdx.x & 31;
  const int h    = blockIdx.x * 4 + w;
  if (h >= H) {                       // pad row 511: zero-fill, no compute
    if (h == H) {
      for (int t = lane; t < L; t += 32) {
        g_yhi[(size_t)H * L + t] = __float2bfloat16(0.0f);
        g_ylo[(size_t)H * L + t] = __float2bfloat16(0.0f);
      }
    }
    return;
  }

  // per-(h,n) ZOH discretization parameters
  const int hn   = h * NST + lane;
  const float dt = expf(log_dt[h]);
  const float Are = -expf(Arl[hn]);
  const float Ai  = Aim[hn];
  const float er  = expf(Are * dt);
  float sb, cbv;
  sincosf(Ai * dt, &sb, &cbv);
  const float wr = er * cbv;
  const float wi = er * sb;
  const float den = Are * Are + Ai * Ai;
  const float wm1 = wr - 1.0f;
  const float qr = (wm1 * Are + wi * Ai) / den;
  const float qi = (wi * Are - wm1 * Ai) / den;
  const float Cr = Cre[hn], Ci = Cim[hn];
  const float cr  = Cr * qr - Ci * qi;
  const float ci  = Cr * qi + Ci * qr;
  const float nci = -ci;
  const float nwi = -wi;
  const float D   = Dsk[h];

  float sr = 0.0f, si = 0.0f;
  float* cb = s_contrib[w];
  float* zb = s_z[w];
  const float* zrow = zin + (size_t)h * L;
  __nv_bfloat16* yh = g_yhi + (size_t)h * L;
  __nv_bfloat16* yl = g_ylo + (size_t)h * L;

  for (int t0 = 0; t0 < L; t0 += 32) {
    const float zv = zrow[t0 + lane];
    zb[lane] = zv;
    __syncwarp();

    float z32[32];
#pragma unroll
    for (int t = 0; t < 32; t++) z32[t] = zb[t];

#pragma unroll
    for (int t = 0; t < 32; t++) {
      const float nsr = fmaf(wr, sr, fmaf(nwi, si, z32[t]));
      const float nsi = fmaf(wr, si, wi * sr);
      sr = nsr; si = nsi;
      cb[t * 33 + lane] = fmaf(cr, sr, nci * si);
    }
    __syncwarp();

    float a0 = 0.f, a1 = 0.f, a2 = 0.f, a3 = 0.f;
    const int base = lane * 33;
#pragma unroll
    for (int n = 0; n < 32; n += 4) {
      a0 += cb[base + n];
      a1 += cb[base + n + 1];
      a2 += cb[base + n + 2];
      a3 += cb[base + n + 3];
    }
    float y = fmaf(D, zv, 2.0f * ((a0 + a1) + (a2 + a3)));

    // tanh-approximation gelu (matches jax.nn.gelu default)
    const float u  = 0.7978845608028654f * fmaf(0.044715f * y, y * y, y);
    const float gl = 0.5f * y * (1.0f + tanhf(u));

    const __nv_bfloat16 hi = __float2bfloat16(gl);
    yh[t0 + lane] = hi;
    yl[t0 + lane] = __float2bfloat16(gl - __bfloat162float(hi));
    __syncwarp();
  }
}

// ---------------------------------------------------------------------------
// Kernel 2: Y2 = W @ Y1 via wmma bf16, 3-product split, fp32 accum.
// CTA tile 128x128, 8 warps of 64x32, K-chunk 16, double-buffered smem.
// ---------------------------------------------------------------------------
namespace {
constexpr int LDA = 24;    // A smem [m][k] row stride (48B: conflict-free ldsm)
constexpr int LDB = 136;   // B smem [k][n] row stride (272B: conflict-free ldsm)
}

__global__ __launch_bounds__(256) void gemm_wmma_kernel(float* __restrict__ Y2) {
  __shared__ __align__(128) __nv_bfloat16 sA[2][2][128 * LDA];  // [buf][hi/lo]
  __shared__ __align__(128) __nv_bfloat16 sB[2][2][16 * LDB];

  const int tid  = threadIdx.x;
  const int warp = tid >> 5;
  const int wm   = warp >> 2;      // 0..1
  const int wn   = warp & 3;       // 0..3
  const int m0   = blockIdx.y * 128;
  const int n0   = blockIdx.x * 128;

  wmma::fragment<wmma::accumulator, 16, 16, 16, float> acc[4][2];
#pragma unroll
  for (int i = 0; i < 4; i++)
#pragma unroll
    for (int j = 0; j < 2; j++) wmma::fill_fragment(acc[i][j], 0.0f);

  // load assignments: A 128x16 per variant -> thread = 1x uint4 (8 bf16)
  const int am = tid >> 1, ak = (tid & 1) * 8;
  const int bk = tid >> 4, bn = (tid & 15) * 8;

  const __nv_bfloat16* Ah = g_whi + (size_t)(m0 + am) * KP + ak;
  const __nv_bfloat16* Al = g_wlo + (size_t)(m0 + am) * KP + ak;
  const __nv_bfloat16* Bh = g_yhi + (size_t)bk * L + n0 + bn;
  const __nv_bfloat16* Bl = g_ylo + (size_t)bk * L + n0 + bn;

  uint4 pah = *(const uint4*)(Ah);
  uint4 pal = *(const uint4*)(Al);
  uint4 pbh = *(const uint4*)(Bh);
  uint4 pbl = *(const uint4*)(Bl);

  *(uint4*)&sA[0][0][am * LDA + ak] = pah;
  *(uint4*)&sA[0][1][am * LDA + ak] = pal;
  *(uint4*)&sB[0][0][bk * LDB + bn] = pbh;
  *(uint4*)&sB[0][1][bk * LDB + bn] = pbl;
  __syncthreads();

  for (int kt = 0; kt < 32; kt++) {
    const int cur = kt & 1, nxt = cur ^ 1;
    const bool more = (kt < 31);
    if (more) {
      const int kc = (kt + 1) * 16;
      pah = *(const uint4*)(Ah + kc);
      pal = *(const uint4*)(Al + kc);
      pbh = *(const uint4*)(Bh + (size_t)kc * L);
      pbl = *(const uint4*)(Bl + (size_t)kc * L);
    }

    wmma::fragment<wmma::matrix_a, 16, 16, 16, __nv_bfloat16, wmma::row_major> fah[4], fal[4];
    wmma::fragment<wmma::matrix_b, 16, 16, 16, __nv_bfloat16, wmma::row_major> fbh[2], fbl[2];
#pragma unroll
    for (int i = 0; i < 4; i++) {
      wmma::load_matrix_sync(fah[i], &sA[cur][0][(wm * 64 + i * 16) * LDA], LDA);
      wmma::load_matrix_sync(fal[i], &sA[cur][1][(wm * 64 + i * 16) * LDA], LDA);
    }
#pragma unroll
    for (int j = 0; j < 2; j++) {
      wmma::load_matrix_sync(fbh[j], &sB[cur][0][wn * 32 + j * 16], LDB);
      wmma::load_matrix_sync(fbl[j], &sB[cur][1][wn * 32 + j * 16], LDB);
    }
#pragma unroll
    for (int i = 0; i < 4; i++)
#pragma unroll
      for (int j = 0; j < 2; j++) {
        wmma::mma_sync(acc[i][j], fah[i], fbh[j], acc[i][j]);
        wmma::mma_sync(acc[i][j], fal[i], fbh[j], acc[i][j]);
        wmma::mma_sync(acc[i][j], fah[i], fbl[j], acc[i][j]);
      }

    if (more) {
      *(uint4*)&sA[nxt][0][am * LDA + ak] = pah;
      *(uint4*)&sA[nxt][1][am * LDA + ak] = pal;
      *(uint4*)&sB[nxt][0][bk * LDB + bn] = pbh;
      *(uint4*)&sB[nxt][1][bk * LDB + bn] = pbl;
    }
    __syncthreads();
  }

#pragma unroll
  for (int i = 0; i < 4; i++)
#pragma unroll
    for (int j = 0; j < 2; j++) {
      float* dst = Y2 + (size_t)(m0 + wm * 64 + i * 16) * L + n0 + wn * 32 + j * 16;
      wmma::store_matrix_sync(dst, acc[i][j], L, wmma::mem_row_major);
    }
}

// ---------------------------------------------------------------------------
// Kernel 3: fused bias + GLU + residual + channel LayerNorm.
// Block: 32 time-cols x 16 h-threads; column staged in dynamic smem.
// ---------------------------------------------------------------------------
__global__ __launch_bounds__(512) void glu_ln_kernel(
    const float* __restrict__ Y2, const float* __restrict__ bg,
    const float* __restrict__ zin, const float* __restrict__ gw,
    const float* __restrict__ bw, float* __restrict__ zout) {
  extern __shared__ float sv[];            // [512][32]
  __shared__ float ssum[16][32];
  __shared__ float ssq[16][32];

  const int tx = threadIdx.x;              // time within tile
  const int ty = threadIdx.y;              // h stride
  const int l  = blockIdx.x * 32 + tx;

  float s = 0.0f, q = 0.0f;
  for (int hh = ty; hh < H; hh += 16) {
    const float a = Y2[(size_t)hh * L + l] + bg[hh];
    const float g = Y2[(size_t)(hh + H) * L + l] + bg[hh + H];
    const float sg = 1.0f / (1.0f + expf(-g));
    const float v = fmaf(a, sg, zin[(size_t)hh * L + l]);
    sv[hh * 32 + tx] = v;
    s += v;
    q = fmaf(v, v, q);
  }
  ssum[ty][tx] = s;
  ssq[ty][tx]  = q;
  __syncthreads();

  float S = 0.0f, Q = 0.0f;
#pragma unroll
  for (int j = 0; j < 16; j++) { S += ssum[j][tx]; Q += ssq[j][tx]; }
  const float mu  = S * (1.0f / (float)H);
  const float var = Q * (1.0f / (float)H) - mu * mu;
  const float inv = rsqrtf(var + 1e-5f);

  for (int hh = ty; hh < H; hh += 16) {
    const float v = sv[hh * 32 + tx];
    zout[(size_t)hh * L + l] = fmaf((v - mu) * inv, gw[hh], bw[hh]);
  }
}

// ---------------------------------------------------------------------------
extern "C" void kernel_launch(void* const* d_in, const int* in_sizes, int n_in,
                              void* d_out, int out_size) {
  const float* Z      = (const float*)d_in[0];
  const float* log_dt = (const float*)d_in[1];
  const float* Arl    = (const float*)d_in[2];
  const float* Aim    = (const float*)d_in[3];
  const float* Cre    = (const float*)d_in[4];
  const float* Cim    = (const float*)d_in[5];
  const float* Dsk    = (const float*)d_in[6];
  const float* Wg     = (const float*)d_in[7];
  const float* bg     = (const float*)d_in[8];
  const float* lng    = (const float*)d_in[9];
  const float* lnb    = (const float*)d_in[10];
  float* out = (float*)d_out;

  float *y2, *zA, *zB;
  cudaGetSymbolAddress((void**)&y2, g_y2);
  cudaGetSymbolAddress((void**)&zA, g_zA);
  cudaGetSymbolAddress((void**)&zB, g_zB);

  static bool attr_done = false;
  if (!attr_done) {
    cudaFuncSetAttribute(glu_ln_kernel,
                         cudaFuncAttributeMaxDynamicSharedMemorySize, 65536);
    attr_done = true;
  }

  // W -> bf16 hi/lo (constant across layers; inside graph, cheap)
  convw_kernel<<<(MP * KP) / 256, 256>>>(Wg);

  const float* zin = Z;
  for (int layer = 0; layer < 4; layer++) {
    float* zout = (layer == 3) ? out : ((layer & 1) ? zB : zA);
    scan_kernel<<<128, 128>>>(zin, log_dt, Arl, Aim, Cre, Cim, Dsk);
    gemm_wmma_kernel<<<dim3(L / 128, MP / 128), 256>>>(y2);
    glu_ln_kernel<<<L / 32, dim3(32, 16), 65536>>>(y2, bg, zin, lng, lnb, zout);
    zin = zout;
  }
}